// round 9
// baseline (speedup 1.0000x reference)
#include <cuda_runtime.h>
#include <cstdint>
#include <math.h>

// Problem constants (fixed by the dataset)
#define NN   50000
#define EE   800000
#define HH   8
#define CCH  32
#define HC   256
#define NB_SCAN 49   // ceil(NN/1024)
#define EST  8       // edge pipeline stages (power of 2)

// ---------------- device scratch (allocation-free: static globals) ----------
__device__ float g_q[(size_t)NN * HC];
__device__ float g_k[(size_t)NN * HC];
__device__ float g_v[(size_t)NN * HC];
__device__ float g_P[(size_t)NN * HH * 256];        // P[n,h,i]
__device__ float g_A[(size_t)NN * HH * 256];        // alpha-weighted ea accumulators
__device__ int   g_deg[NN];
__device__ int   g_off[NN + 1];
__device__ int   g_cur[NN];
__device__ int   g_incl[NN];
__device__ int   g_bsum[64];
__device__ int   g_srcs[EE];
__device__ int   g_perm[EE];
__device__ int   g_is64;

// ---------------- init: dtype sniff + zero degree ---------------------------
__global__ void k_init(const long long* __restrict__ ei) {
    int i = blockIdx.x * blockDim.x + threadIdx.x;
    if (i < NN) g_deg[i] = 0;
    if (i == 0) {
        int ok = 1;
        for (int j = 0; j < 64; j++) {
            long long v = ei[j];
            if (v < 0 || v >= NN) ok = 0;
        }
        g_is64 = ok;
    }
}

__device__ __forceinline__ int load_idx(const void* ei, size_t pos, int is64) {
    if (is64) return (int)((const long long*)ei)[pos];
    return ((const int*)ei)[pos];
}

__global__ void k_hist(const void* __restrict__ ei) {
    int e = blockIdx.x * blockDim.x + threadIdx.x;
    if (e < EE) {
        int d = load_idx(ei, (size_t)EE + e, g_is64);
        if ((unsigned)d < NN) atomicAdd(&g_deg[d], 1);
    }
}

__global__ void k_scan1() {
    __shared__ int sh[1024];
    int t = threadIdx.x;
    int i = blockIdx.x * 1024 + t;
    int v = (i < NN) ? g_deg[i] : 0;
    sh[t] = v;
    __syncthreads();
    #pragma unroll
    for (int off = 1; off < 1024; off <<= 1) {
        int add = (t >= off) ? sh[t - off] : 0;
        __syncthreads();
        sh[t] += add;
        __syncthreads();
    }
    if (i < NN) g_incl[i] = sh[t];
    if (t == 1023) g_bsum[blockIdx.x] = sh[t];
}

// fused scan2+scan3: each block rebuilds the 49-entry block-sum prefix locally
__global__ void k_scan23() {
    __shared__ int bpre[NB_SCAN + 1];
    int t = threadIdx.x;
    if (t == 0) {
        int run = 0;
        for (int b = 0; b < NB_SCAN; b++) { bpre[b] = run; run += g_bsum[b]; }
    }
    __syncthreads();
    int i = blockIdx.x * blockDim.x + t;
    if (i < NN) {
        int incl = g_incl[i] + bpre[i >> 10];
        g_off[i + 1] = incl;
        g_cur[i]     = incl - g_deg[i];
    }
    if (i == 0) g_off[0] = 0;
}

__global__ void k_scatter(const void* __restrict__ ei) {
    int e = blockIdx.x * blockDim.x + threadIdx.x;
    if (e < EE) {
        int is64 = g_is64;
        int d = load_idx(ei, (size_t)EE + e, is64);
        int s = load_idx(ei, (size_t)e, is64);
        if ((unsigned)d < NN && (unsigned)s < NN) {
            int pos = atomicAdd(&g_cur[d], 1);
            if ((unsigned)pos < EE) {
                g_perm[pos] = e;
                g_srcs[pos] = s;
            }
        }
    }
}

// ---------------- fp32 SGEMM 128x128x16, 8x8 register blocking --------------
// which: 0->g_q 1->g_k 2->g_v 3->dout
__global__ __launch_bounds__(256, 2)
void k_sgemm(const float* __restrict__ A, const float* __restrict__ B,
             const float* __restrict__ bias, float* __restrict__ dout,
             int which, int M) {
    float* Cout;
    switch (which) {
        case 0: Cout = g_q; break;
        case 1: Cout = g_k; break;
        case 2: Cout = g_v; break;
        default: Cout = dout; break;
    }

    __shared__ float As[16][128];
    __shared__ float Bs[16][128];

    int t  = threadIdx.x;
    int bm = blockIdx.x * 128;
    int bn = blockIdx.y * 128;
    int tx = t & 15, ty = t >> 4;

    float acc[8][8];
    #pragma unroll
    for (int i = 0; i < 8; i++)
        #pragma unroll
        for (int j = 0; j < 8; j++) acc[i][j] = 0.f;

    int ar = t >> 2,  ac = (t & 3) * 4;
    int bk = t >> 5,  bc = (t & 31) * 4;

    for (int k0 = 0; k0 < 256; k0 += 16) {
        #pragma unroll
        for (int i = 0; i < 2; i++) {
            int row = bm + ar + i * 64;
            int rr  = (row < M) ? row : (M - 1);
            float4 a = *(const float4*)(A + (size_t)rr * 256 + k0 + ac);
            As[ac + 0][ar + i * 64] = a.x;
            As[ac + 1][ar + i * 64] = a.y;
            As[ac + 2][ar + i * 64] = a.z;
            As[ac + 3][ar + i * 64] = a.w;
        }
        #pragma unroll
        for (int i = 0; i < 2; i++) {
            float4 b = *(const float4*)(B + (size_t)(k0 + bk + i * 8) * 256 + bn + bc);
            *(float4*)&Bs[bk + i * 8][bc] = b;
        }
        __syncthreads();
        #pragma unroll
        for (int kk = 0; kk < 16; kk++) {
            float ra[8], rb[8];
            *(float4*)(ra)     = *(float4*)&As[kk][ty * 8];
            *(float4*)(ra + 4) = *(float4*)&As[kk][ty * 8 + 4];
            *(float4*)(rb)     = *(float4*)&Bs[kk][tx * 8];
            *(float4*)(rb + 4) = *(float4*)&Bs[kk][tx * 8 + 4];
            #pragma unroll
            for (int i = 0; i < 8; i++)
                #pragma unroll
                for (int j = 0; j < 8; j++)
                    acc[i][j] = fmaf(ra[i], rb[j], acc[i][j]);
        }
        __syncthreads();
    }

    float bb[8];
    #pragma unroll
    for (int j = 0; j < 8; j++) bb[j] = bias[bn + tx * 8 + j];

    #pragma unroll
    for (int i = 0; i < 8; i++) {
        int row = bm + ty * 8 + i;
        if (row < M) {
            float* cptr = Cout + (size_t)row * 256 + bn + tx * 8;
            float4 o0, o1;
            o0.x = acc[i][0] + bb[0]; o0.y = acc[i][1] + bb[1];
            o0.z = acc[i][2] + bb[2]; o0.w = acc[i][3] + bb[3];
            o1.x = acc[i][4] + bb[4]; o1.y = acc[i][5] + bb[5];
            o1.z = acc[i][6] + bb[6]; o1.w = acc[i][7] + bb[7];
            *(float4*)(cptr)     = o0;
            *(float4*)(cptr + 4) = o1;
        }
    }
}

// ---------------- P GEMM: P[n,h,i] = sum_c q[n,h*32+c] * We[i,h*32+c] -------
__global__ __launch_bounds__(256)
void k_pgemm(const float* __restrict__ We) {
    __shared__ float qs[64][33];
    __shared__ float Wt[32][257];
    int h  = blockIdx.y;
    int n0 = blockIdx.x * 64;
    int t  = threadIdx.x;

    for (int idx = t; idx < 64 * 32; idx += 256) {
        int node = idx >> 5, c = idx & 31;
        int n = n0 + node;
        qs[node][c] = (n < NN) ? g_q[(size_t)n * 256 + h * 32 + c] : 0.f;
    }
    for (int idx = t; idx < 256 * 32; idx += 256) {
        int i = idx >> 5, c = idx & 31;
        Wt[c][i] = We[(size_t)i * 256 + h * 32 + c];
    }
    __syncthreads();

    int tx = t & 31;
    int ty = t >> 5;
    float acc[8][8];
    #pragma unroll
    for (int r = 0; r < 8; r++)
        #pragma unroll
        for (int ii = 0; ii < 8; ii++) acc[r][ii] = 0.f;

    #pragma unroll 4
    for (int c = 0; c < 32; c++) {
        float a[8], b[8];
        #pragma unroll
        for (int r = 0; r < 8; r++) a[r] = qs[ty * 8 + r][c];
        #pragma unroll
        for (int ii = 0; ii < 8; ii++) b[ii] = Wt[c][tx + ii * 32];
        #pragma unroll
        for (int r = 0; r < 8; r++)
            #pragma unroll
            for (int ii = 0; ii < 8; ii++)
                acc[r][ii] = fmaf(a[r], b[ii], acc[r][ii]);
    }

    #pragma unroll
    for (int r = 0; r < 8; r++) {
        int n = n0 + ty * 8 + r;
        if (n < NN) {
            float* Pr = g_P + ((size_t)n * 8 + h) * 256;
            #pragma unroll
            for (int ii = 0; ii < 8; ii++)
                __stcs(Pr + tx + ii * 32, acc[r][ii]);
        }
    }
}

// ---------------- edge pass: cp.async ring + reg-pipelined k/v --------------
__device__ __forceinline__ void cp_async16(unsigned smem, const void* g) {
    asm volatile("cp.async.cg.shared.global [%0], [%1], 16;\n"
                 :: "r"(smem), "l"(g) : "memory");
}
__device__ __forceinline__ void cp_commit() {
    asm volatile("cp.async.commit_group;\n" ::: "memory");
}
template <int N>
__device__ __forceinline__ void cp_wait() {
    asm volatile("cp.async.wait_group %0;\n" :: "n"(N) : "memory");
}

__global__ __launch_bounds__(256, 3)
void k_edge(const float* __restrict__ ea, float* __restrict__ out) {
    __shared__ float eas[EST][256];
    int n    = blockIdx.x;
    int t    = threadIdx.x;
    int h    = t >> 5;
    int lane = t & 31;

    int begin = g_off[n], end = g_off[n + 1];
    size_t nb = (size_t)n * 256 + h * 32 + lane;
    const float scale = 0.17677669529663687f;     // 1/sqrt(32)
    float qv = g_q[nb] * scale;

    const float* Pr = g_P + ((size_t)n * 8 + h) * 256;
    float preg[8];
    #pragma unroll
    for (int j = 0; j < 8; j++) preg[j] = __ldcs(Pr + j * 32 + lane) * scale;

    float m = -INFINITY, l = 0.f, vacc = 0.f;
    float A[8];
    #pragma unroll
    for (int j = 0; j < 8; j++) A[j] = 0.f;

    unsigned smem_row = (unsigned)__cvta_generic_to_shared(&eas[0][0]);
    int cth = t & 63;  // 64 copy threads x 16B cover a 1KB row

    auto prefetch = [&](int ip) {
        if (ip < end && t < 64) {
            int eo = g_perm[ip];
            cp_async16(smem_row + (ip & (EST - 1)) * 1024 + cth * 16,
                       ea + (size_t)eo * 256 + cth * 4);
        }
        cp_commit();
    };

    #pragma unroll
    for (int j = 0; j < EST - 1; j++) prefetch(begin + j);

    // register-pipelined k/v: preload edge `begin`
    float kv_cur = 0.f, vv_cur = 0.f;
    if (begin < end) {
        size_t sb = (size_t)g_srcs[begin] * 256 + h * 32 + lane;
        kv_cur = g_k[sb];
        vv_cur = g_v[sb];
    }

    for (int i = begin; i < end; i++) {
        // issue next edge's k/v loads immediately (full iteration of slack)
        float kv_nxt = 0.f, vv_nxt = 0.f;
        if (i + 1 < end) {
            size_t sbn = (size_t)g_srcs[i + 1] * 256 + h * 32 + lane;
            kv_nxt = g_k[sbn];
            vv_nxt = g_v[sbn];
        }

        cp_wait<EST - 2>();      // edge i's ea stage has landed
        __syncthreads();         // publish; retires readers of stage (i-1)%EST
        prefetch(i + EST - 1);   // refill the just-retired stage

        const float* eb = eas[i & (EST - 1)];
        float er[8];
        #pragma unroll
        for (int j = 0; j < 8; j++) er[j] = eb[j * 32 + lane];

        float s = qv * kv_cur;
        #pragma unroll
        for (int j = 0; j < 8; j++) s = fmaf(preg[j], er[j], s);
        #pragma unroll
        for (int o = 16; o; o >>= 1) s += __shfl_xor_sync(0xffffffffu, s, o);

        float nm = fmaxf(m, s);
        float cf = __expf(m - nm);
        float p  = __expf(s - nm);
        l    = l * cf + p;
        vacc = vacc * cf + p * vv_cur;
        #pragma unroll
        for (int j = 0; j < 8; j++) A[j] = fmaf(A[j], cf, p * er[j]);
        m = nm;

        kv_cur = kv_nxt;
        vv_cur = vv_nxt;
    }
    cp_wait<0>();

    float inv = (l > 0.f) ? (1.f / l) : 0.f;
    out[nb] += vacc * inv;
    float* Ar = g_A + ((size_t)n * 8 + h) * 256;
    #pragma unroll
    for (int j = 0; j < 8; j++) __stcs(Ar + j * 32 + lane, A[j] * inv);
}

// ---------------- A GEMM: out[n,h*32+c] += sum_i A[n,h,i] * We[i,h*32+c] ----
__global__ __launch_bounds__(256)
void k_agemm(const float* __restrict__ We, float* __restrict__ out) {
    __shared__ float As[64][65];
    __shared__ float Ws[64][33];
    int h  = blockIdx.y;
    int n0 = blockIdx.x * 64;
    int t  = threadIdx.x;
    int tx = t & 31;
    int ty = t >> 5;

    float acc[8];
    #pragma unroll
    for (int r = 0; r < 8; r++) acc[r] = 0.f;

    for (int k0 = 0; k0 < 256; k0 += 64) {
        __syncthreads();
        for (int idx = t; idx < 64 * 64; idx += 256) {
            int node = idx >> 6, kk = idx & 63;
            int n = n0 + node;
            As[node][kk] = (n < NN)
                ? __ldcs(g_A + ((size_t)n * 8 + h) * 256 + k0 + kk) : 0.f;
        }
        for (int idx = t; idx < 64 * 32; idx += 256) {
            int kk = idx >> 5, c = idx & 31;
            Ws[kk][c] = We[(size_t)(k0 + kk) * 256 + h * 32 + c];
        }
        __syncthreads();
        #pragma unroll 8
        for (int kk = 0; kk < 64; kk++) {
            float b = Ws[kk][tx];
            #pragma unroll
            for (int r = 0; r < 8; r++)
                acc[r] = fmaf(As[ty * 8 + r][kk], b, acc[r]);
        }
    }

    #pragma unroll
    for (int r = 0; r < 8; r++) {
        int n = n0 + ty * 8 + r;
        if (n < NN)
            out[(size_t)n * 256 + h * 32 + tx] += acc[r];
    }
}

// ---------------- launch ----------------------------------------------------
extern "C" void kernel_launch(void* const* d_in, const int* in_sizes, int n_in,
                              void* d_out, int out_size) {
    const float* x  = (const float*)d_in[0];
    const void*  ei = d_in[1];
    const float* ea = (const float*)d_in[2];
    const float* Wq = (const float*)d_in[3];
    const float* bq = (const float*)d_in[4];
    const float* Wk = (const float*)d_in[5];
    const float* bk = (const float*)d_in[6];
    const float* Wv = (const float*)d_in[7];
    const float* bv = (const float*)d_in[8];
    const float* We = (const float*)d_in[9];
    const float* Ws = (const float*)d_in[10];
    const float* bs = (const float*)d_in[11];
    float* out = (float*)d_out;

    // 0-1) init (dtype sniff + zero degrees), histogram
    k_init<<<(NN + 255) / 256, 256>>>((const long long*)ei);
    k_hist<<<(EE + 255) / 256, 256>>>(ei);

    // 2-5) node GEMMs
    dim3 gn((NN + 127) / 128, 2);
    k_sgemm<<<gn, 256>>>(x, Wq, bq, out, 0, NN);
    k_sgemm<<<gn, 256>>>(x, Wk, bk, out, 1, NN);
    k_sgemm<<<gn, 256>>>(x, Wv, bv, out, 2, NN);
    k_sgemm<<<gn, 256>>>(x, Ws, bs, out, 3, NN);

    // 6-8) finish CSR sort
    k_scan1<<<NB_SCAN, 1024>>>();
    k_scan23<<<(NN + 255) / 256, 256>>>();
    k_scatter<<<(EE + 255) / 256, 256>>>(ei);

    // 9) P[n,h,i] = We_h @ q_h
    dim3 gp((NN + 63) / 64, 8);
    k_pgemm<<<gp, 256>>>(We);

    // 10) pipelined edge pass
    k_edge<<<NN, 256>>>(ea, out);

    // 11) out += A @ We
    k_agemm<<<gp, 256>>>(We, out);
}

// round 12
// speedup vs baseline: 1.2390x; 1.2390x over previous
#include <cuda_runtime.h>
#include <cuda_bf16.h>
#include <mma.h>
#include <cstdint>
#include <math.h>

using namespace nvcuda;

// Problem constants (fixed by the dataset)
#define NN   50000
#define EE   800000
#define HH   8
#define CCH  32
#define HC   256
#define NB_SCAN 49   // ceil(NN/1024)
#define EST  4       // edge pipeline stages

// ---------------- device scratch (allocation-free: static globals) ----------
__device__ float g_q[(size_t)NN * HC];
__device__ float g_k[(size_t)NN * HC];
__device__ float g_v[(size_t)NN * HC];
__device__ float g_P[(size_t)NN * HH * 256];
__device__ float g_A[(size_t)NN * HH * 256];
__device__ unsigned short g_xhi[(size_t)NN * HC];   // bf16 hi split of x
__device__ unsigned short g_xlo[(size_t)NN * HC];   // bf16 lo split of x
__device__ unsigned short g_whi[4 * 65536];         // bf16 hi of Wq,Wk,Wv,Ws
__device__ unsigned short g_wlo[4 * 65536];
__device__ int   g_deg[NN];
__device__ int   g_off[NN + 1];
__device__ int   g_cur[NN];
__device__ int   g_incl[NN];
__device__ int   g_bsum[64];
__device__ int   g_srcs[EE];
__device__ int   g_perm[EE];
__device__ int   g_is64;

// ---------------- bf16 split helpers -----------------------------------------
static __device__ __forceinline__ unsigned short bf16b(float v) {
    __nv_bfloat16 b = __float2bfloat16(v);
    return *reinterpret_cast<unsigned short*>(&b);
}
static __device__ __forceinline__ float bf16f(unsigned short u) {
    __nv_bfloat16 b = *reinterpret_cast<__nv_bfloat16*>(&u);
    return __bfloat162float(b);
}

// ---------------- init: dtype sniff + zero degree ---------------------------
__global__ void k_init(const long long* __restrict__ ei) {
    int i = blockIdx.x * blockDim.x + threadIdx.x;
    if (i < NN) g_deg[i] = 0;
    if (i == 0) {
        int ok = 1;
        for (int j = 0; j < 64; j++) {
            long long v = ei[j];
            if (v < 0 || v >= NN) ok = 0;
        }
        g_is64 = ok;
    }
}

__device__ __forceinline__ int load_idx(const void* ei, size_t pos, int is64) {
    if (is64) return (int)((const long long*)ei)[pos];
    return ((const int*)ei)[pos];
}

__global__ void k_hist(const void* __restrict__ ei) {
    int e = blockIdx.x * blockDim.x + threadIdx.x;
    if (e < EE) {
        int d = load_idx(ei, (size_t)EE + e, g_is64);
        if ((unsigned)d < NN) atomicAdd(&g_deg[d], 1);
    }
}

// ---------------- fp32 -> bf16 hi/lo conversion ------------------------------
__global__ void k_cvt_x(const float* __restrict__ x) {
    size_t i = ((size_t)blockIdx.x * blockDim.x + threadIdx.x) * 8;
    if (i >= (size_t)NN * HC) return;
    float4 v0 = *(const float4*)(x + i);
    float4 v1 = *(const float4*)(x + i + 4);
    float f[8] = {v0.x, v0.y, v0.z, v0.w, v1.x, v1.y, v1.z, v1.w};
    unsigned short h[8], l[8];
    #pragma unroll
    for (int j = 0; j < 8; j++) {
        h[j] = bf16b(f[j]);
        l[j] = bf16b(f[j] - bf16f(h[j]));
    }
    uint4 hp, lp;
    hp.x = h[0] | ((unsigned)h[1] << 16); hp.y = h[2] | ((unsigned)h[3] << 16);
    hp.z = h[4] | ((unsigned)h[5] << 16); hp.w = h[6] | ((unsigned)h[7] << 16);
    lp.x = l[0] | ((unsigned)l[1] << 16); lp.y = l[2] | ((unsigned)l[3] << 16);
    lp.z = l[4] | ((unsigned)l[5] << 16); lp.w = l[6] | ((unsigned)l[7] << 16);
    *(uint4*)(g_xhi + i) = hp;
    *(uint4*)(g_xlo + i) = lp;
}

__global__ void k_cvt_w(const float* __restrict__ W0, const float* __restrict__ W1,
                        const float* __restrict__ W2, const float* __restrict__ W3) {
    int w = blockIdx.y;
    const float* W = (w == 0) ? W0 : (w == 1) ? W1 : (w == 2) ? W2 : W3;
    size_t i = ((size_t)blockIdx.x * blockDim.x + threadIdx.x) * 8;
    if (i >= 65536) return;
    float4 v0 = *(const float4*)(W + i);
    float4 v1 = *(const float4*)(W + i + 4);
    float f[8] = {v0.x, v0.y, v0.z, v0.w, v1.x, v1.y, v1.z, v1.w};
    unsigned short h[8], l[8];
    #pragma unroll
    for (int j = 0; j < 8; j++) {
        h[j] = bf16b(f[j]);
        l[j] = bf16b(f[j] - bf16f(h[j]));
    }
    uint4 hp, lp;
    hp.x = h[0] | ((unsigned)h[1] << 16); hp.y = h[2] | ((unsigned)h[3] << 16);
    hp.z = h[4] | ((unsigned)h[5] << 16); hp.w = h[6] | ((unsigned)h[7] << 16);
    lp.x = l[0] | ((unsigned)l[1] << 16); lp.y = l[2] | ((unsigned)l[3] << 16);
    lp.z = l[4] | ((unsigned)l[5] << 16); lp.w = l[6] | ((unsigned)l[7] << 16);
    *(uint4*)(g_whi + (size_t)w * 65536 + i) = hp;
    *(uint4*)(g_wlo + (size_t)w * 65536 + i) = lp;
}

// ---------------- scan/scatter (unchanged) -----------------------------------
__global__ void k_scan1() {
    __shared__ int sh[1024];
    int t = threadIdx.x;
    int i = blockIdx.x * 1024 + t;
    int v = (i < NN) ? g_deg[i] : 0;
    sh[t] = v;
    __syncthreads();
    #pragma unroll
    for (int off = 1; off < 1024; off <<= 1) {
        int add = (t >= off) ? sh[t - off] : 0;
        __syncthreads();
        sh[t] += add;
        __syncthreads();
    }
    if (i < NN) g_incl[i] = sh[t];
    if (t == 1023) g_bsum[blockIdx.x] = sh[t];
}

__global__ void k_scan23() {
    __shared__ int bpre[NB_SCAN + 1];
    int t = threadIdx.x;
    if (t == 0) {
        int run = 0;
        for (int b = 0; b < NB_SCAN; b++) { bpre[b] = run; run += g_bsum[b]; }
    }
    __syncthreads();
    int i = blockIdx.x * blockDim.x + t;
    if (i < NN) {
        int incl = g_incl[i] + bpre[i >> 10];
        g_off[i + 1] = incl;
        g_cur[i]     = incl - g_deg[i];
    }
    if (i == 0) g_off[0] = 0;
}

__global__ void k_scatter(const void* __restrict__ ei) {
    int e = blockIdx.x * blockDim.x + threadIdx.x;
    if (e < EE) {
        int is64 = g_is64;
        int d = load_idx(ei, (size_t)EE + e, is64);
        int s = load_idx(ei, (size_t)e, is64);
        if ((unsigned)d < NN && (unsigned)s < NN) {
            int pos = atomicAdd(&g_cur[d], 1);
            if ((unsigned)pos < EE) {
                g_perm[pos] = e;
                g_srcs[pos] = s;
            }
        }
    }
}

// =================== WMMA bf16 3-split node GEMM ============================
// D[128,128] tile = x[128,256] @ W[256,256] + bias; blockIdx.z picks weights.
// D = Ahi@Bhi + Ahi@Blo + Alo@Bhi, accumulated in fp32 wmma fragments.
#define A_LD 40     // smem row stride (ushorts) for 32-col A chunk
#define B_LD 136    // smem row stride (ushorts) for 128-col B chunk

__global__ __launch_bounds__(256, 2)
void k_wgemm(const float* __restrict__ bq, const float* __restrict__ bk,
             const float* __restrict__ bv, const float* __restrict__ bs,
             float* __restrict__ dout) {
    __shared__ float biasT[16 * 128];                 // bias broadcast / tail staging
    __shared__ unsigned short Ahi[128 * A_LD], Alo[128 * A_LD];
    __shared__ unsigned short Bhi[32 * B_LD],  Blo[32 * B_LD];

    int w = blockIdx.z;
    const float* bias; float* Cout;
    switch (w) {
        case 0:  bias = bq; Cout = g_q;  break;
        case 1:  bias = bk; Cout = g_k;  break;
        case 2:  bias = bv; Cout = g_v;  break;
        default: bias = bs; Cout = dout; break;
    }
    int bm = blockIdx.x * 128, bn = blockIdx.y * 128;
    int t = threadIdx.x, wi = t >> 5;
    int wm = wi & 1, wn = wi >> 1;   // warp covers rows [wm*64, +64), cols [wn*32, +32)

    for (int i = t; i < 2048; i += 256) biasT[i] = bias[bn + (i & 127)];
    __syncthreads();

    wmma::fragment<wmma::accumulator, 16, 16, 16, float> acc[4][2];
    #pragma unroll
    for (int mi = 0; mi < 4; mi++)
        #pragma unroll
        for (int ni = 0; ni < 2; ni++)
            wmma::load_matrix_sync(acc[mi][ni], biasT + wn * 32 + ni * 16, 128,
                                   wmma::mem_row_major);

    const unsigned short* wh = g_whi + (size_t)w * 65536;
    const unsigned short* wl = g_wlo + (size_t)w * 65536;

    for (int kc = 0; kc < 8; kc++) {
        int k0 = kc * 32;
        #pragma unroll
        for (int j = 0; j < 2; j++) {                 // A chunk: 128 x 32
            int idx = t + j * 256;
            int row = idx >> 2, c8 = (idx & 3) * 8;
            int rr = bm + row; if (rr >= NN) rr = NN - 1;
            *(uint4*)(Ahi + row * A_LD + c8) =
                *(const uint4*)(g_xhi + (size_t)rr * 256 + k0 + c8);
            *(uint4*)(Alo + row * A_LD + c8) =
                *(const uint4*)(g_xlo + (size_t)rr * 256 + k0 + c8);
        }
        #pragma unroll
        for (int j = 0; j < 2; j++) {                 // B chunk: 32 x 128
            int idx = t + j * 256;
            int kk = idx >> 4, c8 = (idx & 15) * 8;
            *(uint4*)(Bhi + kk * B_LD + c8) =
                *(const uint4*)(wh + (size_t)(k0 + kk) * 256 + bn + c8);
            *(uint4*)(Blo + kk * B_LD + c8) =
                *(const uint4*)(wl + (size_t)(k0 + kk) * 256 + bn + c8);
        }
        __syncthreads();

        #pragma unroll
        for (int ks = 0; ks < 2; ks++) {
            wmma::fragment<wmma::matrix_b, 16, 16, 16, __nv_bfloat16, wmma::row_major> fbh[2], fbl[2];
            #pragma unroll
            for (int ni = 0; ni < 2; ni++) {
                wmma::load_matrix_sync(fbh[ni],
                    (const __nv_bfloat16*)(Bhi + ks * 16 * B_LD + wn * 32 + ni * 16), B_LD);
                wmma::load_matrix_sync(fbl[ni],
                    (const __nv_bfloat16*)(Blo + ks * 16 * B_LD + wn * 32 + ni * 16), B_LD);
            }
            #pragma unroll
            for (int mi = 0; mi < 4; mi++) {
                wmma::fragment<wmma::matrix_a, 16, 16, 16, __nv_bfloat16, wmma::row_major> fah, fal;
                wmma::load_matrix_sync(fah,
                    (const __nv_bfloat16*)(Ahi + (wm * 64 + mi * 16) * A_LD + ks * 16), A_LD);
                wmma::load_matrix_sync(fal,
                    (const __nv_bfloat16*)(Alo + (wm * 64 + mi * 16) * A_LD + ks * 16), A_LD);
                #pragma unroll
                for (int ni = 0; ni < 2; ni++) {
                    wmma::mma_sync(acc[mi][ni], fah, fbh[ni], acc[mi][ni]);
                    wmma::mma_sync(acc[mi][ni], fah, fbl[ni], acc[mi][ni]);
                    wmma::mma_sync(acc[mi][ni], fal, fbh[ni], acc[mi][ni]);
                }
            }
        }
        __syncthreads();
    }

    if (bm + 128 <= NN) {
        #pragma unroll
        for (int mi = 0; mi < 4; mi++)
            #pragma unroll
            for (int ni = 0; ni < 2; ni++)
                wmma::store_matrix_sync(
                    Cout + (size_t)(bm + wm * 64 + mi * 16) * 256 + bn + wn * 32 + ni * 16,
                    acc[mi][ni], 256, wmma::mem_row_major);
    } else {
        float* stg = biasT + wi * 256;   // 16x16 per-warp staging (biasT reuse)
        int lane = t & 31;
        for (int mi = 0; mi < 4; mi++)
            for (int ni = 0; ni < 2; ni++) {
                wmma::store_matrix_sync(stg, acc[mi][ni], 16, wmma::mem_row_major);
                __syncwarp();
                for (int e = lane; e < 256; e += 32) {
                    int r = e >> 4, c = e & 15;
                    int row = bm + wm * 64 + mi * 16 + r;
                    if (row < NN)
                        Cout[(size_t)row * 256 + bn + wn * 32 + ni * 16 + c] = stg[e];
                }
                __syncwarp();
            }
    }
}

// ---------------- P GEMM: P[n,h,i] = sum_c q[n,h*32+c] * We[i,h*32+c] -------
__global__ __launch_bounds__(256)
void k_pgemm(const float* __restrict__ We) {
    __shared__ float qs[64][33];
    __shared__ float Wt[32][257];
    int h  = blockIdx.y;
    int n0 = blockIdx.x * 64;
    int t  = threadIdx.x;

    for (int idx = t; idx < 64 * 32; idx += 256) {
        int node = idx >> 5, c = idx & 31;
        int n = n0 + node;
        qs[node][c] = (n < NN) ? g_q[(size_t)n * 256 + h * 32 + c] : 0.f;
    }
    for (int idx = t; idx < 256 * 32; idx += 256) {
        int i = idx >> 5, c = idx & 31;
        Wt[c][i] = We[(size_t)i * 256 + h * 32 + c];
    }
    __syncthreads();

    int tx = t & 31;
    int ty = t >> 5;
    float acc[8][8];
    #pragma unroll
    for (int r = 0; r < 8; r++)
        #pragma unroll
        for (int ii = 0; ii < 8; ii++) acc[r][ii] = 0.f;

    #pragma unroll 4
    for (int c = 0; c < 32; c++) {
        float a[8], b[8];
        #pragma unroll
        for (int r = 0; r < 8; r++) a[r] = qs[ty * 8 + r][c];
        #pragma unroll
        for (int ii = 0; ii < 8; ii++) b[ii] = Wt[c][tx + ii * 32];
        #pragma unroll
        for (int r = 0; r < 8; r++)
            #pragma unroll
            for (int ii = 0; ii < 8; ii++)
                acc[r][ii] = fmaf(a[r], b[ii], acc[r][ii]);
    }

    #pragma unroll
    for (int r = 0; r < 8; r++) {
        int n = n0 + ty * 8 + r;
        if (n < NN) {
            float* Pr = g_P + ((size_t)n * 8 + h) * 256;
            #pragma unroll
            for (int ii = 0; ii < 8; ii++)
                __stcs(Pr + tx + ii * 32, acc[r][ii]);
        }
    }
}

// ---------------- edge pass: cp.async 4-stage pipeline (round-7 version) ----
__device__ __forceinline__ void cp_async16(unsigned smem, const void* g) {
    asm volatile("cp.async.cg.shared.global [%0], [%1], 16;\n"
                 :: "r"(smem), "l"(g) : "memory");
}
__device__ __forceinline__ void cp_commit() {
    asm volatile("cp.async.commit_group;\n" ::: "memory");
}
template <int N>
__device__ __forceinline__ void cp_wait() {
    asm volatile("cp.async.wait_group %0;\n" :: "n"(N) : "memory");
}

__global__ __launch_bounds__(256)
void k_edge(const float* __restrict__ ea, float* __restrict__ out) {
    __shared__ float eas[EST][256];
    int n    = blockIdx.x;
    int t    = threadIdx.x;
    int h    = t >> 5;
    int lane = t & 31;

    int begin = g_off[n], end = g_off[n + 1];
    size_t nb = (size_t)n * 256 + h * 32 + lane;
    const float scale = 0.17677669529663687f;     // 1/sqrt(32)
    float qv = g_q[nb] * scale;

    const float* Pr = g_P + ((size_t)n * 8 + h) * 256;
    float preg[8];
    #pragma unroll
    for (int j = 0; j < 8; j++) preg[j] = __ldcs(Pr + j * 32 + lane) * scale;

    float m = -INFINITY, l = 0.f, vacc = 0.f;
    float A[8];
    #pragma unroll
    for (int j = 0; j < 8; j++) A[j] = 0.f;

    unsigned smem_row = (unsigned)__cvta_generic_to_shared(&eas[0][0]);
    int cth = t & 63;

    auto prefetch = [&](int ip) {
        if (ip < end && t < 64) {
            int eo = g_perm[ip];
            cp_async16(smem_row + (ip & (EST - 1)) * 1024 + cth * 16,
                       ea + (size_t)eo * 256 + cth * 4);
        }
        cp_commit();
    };

    #pragma unroll
    for (int j = 0; j < EST - 1; j++) prefetch(begin + j);

    for (int i = begin; i < end; i++) {
        cp_wait<EST - 2>();
        __syncthreads();
        prefetch(i + EST - 1);

        int src = g_srcs[i];
        size_t sb = (size_t)src * 256 + h * 32 + lane;
        float kv = g_k[sb];
        float vv = g_v[sb];

        const float* eb = eas[i & (EST - 1)];
        float er[8];
        #pragma unroll
        for (int j = 0; j < 8; j++) er[j] = eb[j * 32 + lane];

        float s = qv * kv;
        #pragma unroll
        for (int j = 0; j < 8; j++) s = fmaf(preg[j], er[j], s);
        #pragma unroll
        for (int o = 16; o; o >>= 1) s += __shfl_xor_sync(0xffffffffu, s, o);

        float nm = fmaxf(m, s);
        float cf = __expf(m - nm);
        float p  = __expf(s - nm);
        l    = l * cf + p;
        vacc = vacc * cf + p * vv;
        #pragma unroll
        for (int j = 0; j < 8; j++) A[j] = fmaf(A[j], cf, p * er[j]);
        m = nm;
    }
    cp_wait<0>();

    float inv = (l > 0.f) ? (1.f / l) : 0.f;
    out[nb] += vacc * inv;
    float* Ar = g_A + ((size_t)n * 8 + h) * 256;
    #pragma unroll
    for (int j = 0; j < 8; j++) Ar[j * 32 + lane] = A[j] * inv;
}

// ---------------- A GEMM: out[n,h*32+c] += sum_i A[n,h,i] * We[i,h*32+c] ----
__global__ __launch_bounds__(256)
void k_agemm(const float* __restrict__ We, float* __restrict__ out) {
    __shared__ float As[64][65];
    __shared__ float Ws[64][33];
    int h  = blockIdx.y;
    int n0 = blockIdx.x * 64;
    int t  = threadIdx.x;
    int tx = t & 31;
    int ty = t >> 5;

    float acc[8];
    #pragma unroll
    for (int r = 0; r < 8; r++) acc[r] = 0.f;

    for (int k0 = 0; k0 < 256; k0 += 64) {
        __syncthreads();
        for (int idx = t; idx < 64 * 64; idx += 256) {
            int node = idx >> 6, kk = idx & 63;
            int n = n0 + node;
            As[node][kk] = (n < NN)
                ? __ldcs(g_A + ((size_t)n * 8 + h) * 256 + k0 + kk) : 0.f;
        }
        for (int idx = t; idx < 64 * 32; idx += 256) {
            int kk = idx >> 5, c = idx & 31;
            Ws[kk][c] = We[(size_t)(k0 + kk) * 256 + h * 32 + c];
        }
        __syncthreads();
        #pragma unroll 8
        for (int kk = 0; kk < 64; kk++) {
            float b = Ws[kk][tx];
            #pragma unroll
            for (int r = 0; r < 8; r++)
                acc[r] = fmaf(As[ty * 8 + r][kk], b, acc[r]);
        }
    }

    #pragma unroll
    for (int r = 0; r < 8; r++) {
        int n = n0 + ty * 8 + r;
        if (n < NN)
            out[(size_t)n * 256 + h * 32 + tx] += acc[r];
    }
}

// ---------------- launch ----------------------------------------------------
extern "C" void kernel_launch(void* const* d_in, const int* in_sizes, int n_in,
                              void* d_out, int out_size) {
    const float* x  = (const float*)d_in[0];
    const void*  ei = d_in[1];
    const float* ea = (const float*)d_in[2];
    const float* Wq = (const float*)d_in[3];
    const float* bq = (const float*)d_in[4];
    const float* Wk = (const float*)d_in[5];
    const float* bk = (const float*)d_in[6];
    const float* Wv = (const float*)d_in[7];
    const float* bv = (const float*)d_in[8];
    const float* We = (const float*)d_in[9];
    const float* Ws = (const float*)d_in[10];
    const float* bs = (const float*)d_in[11];
    float* out = (float*)d_out;

    // 0-4: init, hist, x/W bf16-split conversion, scan1
    k_init<<<(NN + 255) / 256, 256>>>((const long long*)ei);
    k_hist<<<(EE + 255) / 256, 256>>>(ei);
    k_cvt_x<<<(NN * HC / 8 + 255) / 256, 256>>>(x);
    k_cvt_w<<<dim3(65536 / 8 / 256, 4), 256>>>(Wq, Wk, Wv, Ws);
    k_scan1<<<NB_SCAN, 1024>>>();

    // 5: all four node GEMMs on HMMA tensor cores (ncu -s 5 lands here)
    dim3 gg((NN + 127) / 128, 2, 4);
    k_wgemm<<<gg, 256>>>(bq, bk, bv, bs, out);

    // finish CSR sort
    k_scan23<<<(NN + 255) / 256, 256>>>();
    k_scatter<<<(EE + 255) / 256, 256>>>(ei);

    // P projection, edge pass, A GEMM
    dim3 gp((NN + 63) / 64, 8);
    k_pgemm<<<gp, 256>>>(We);
    k_edge<<<NN, 256>>>(ea, out);
    k_agemm<<<gp, 256>>>(We, out);
}